// round 16
// baseline (speedup 1.0000x reference)
#include <cuda_runtime.h>
#include <math.h>

#define IMG_H 2048
#define IMG_W 2048
#define HW (IMG_H * IMG_W)
#define THRESH 10.0f

// 180 / 3.14159 (reference constant, NOT pi)
#define RAD2DEG_D 57.29582790879777437539

// Octant boundary tangents (see R7 derivation)
#define T1_POS 0.41421317376f
#define T2_POS 2.41420677f
#define T1_NEG 0.41421628f
#define T2_NEG 2.41422489f
#define BAND1 1.0e-3f
#define BAND2 6.0e-3f

__device__ __forceinline__ float ldz_g(const float* __restrict__ p, int Y, int X) {
    return (Y >= 0 && Y < IMG_H && X >= 0 && X < IMG_W) ? __ldg(p + Y * IMG_W + X) : 0.0f;
}

__device__ __forceinline__ float sqrt_approx(float x) {
    float r;
    asm("sqrt.approx.f32 %0, %1;" : "=f"(r) : "f"(x));
    return r;
}

// ---------------------------------------------------------------------------
// Exact (fp64) helpers reading the global blurred map (zero-padded).
// ---------------------------------------------------------------------------
__device__ __noinline__ void sobel_exact_g(const float* __restrict__ blurred,
                                           int Y, int X,
                                           double& ogx, double& ogy, double& omag) {
    double gxs = 0.0, gys = 0.0, mg = 0.0;
#pragma unroll
    for (int c = 0; c < 3; c++) {
        const float* __restrict__ p = blurred + c * HW;
        const double a  = ldz_g(p, Y - 1, X - 1);
        const double b  = ldz_g(p, Y - 1, X    );
        const double cc = ldz_g(p, Y - 1, X + 1);
        const double d  = ldz_g(p, Y,     X - 1);
        const double e  = ldz_g(p, Y,     X + 1);
        const double f  = ldz_g(p, Y + 1, X - 1);
        const double g  = ldz_g(p, Y + 1, X    );
        const double h  = ldz_g(p, Y + 1, X + 1);
        const double gx = (a - cc) + 2.0 * (d - e) + (f - h);
        const double gy = (a + 2.0 * b + cc) - (f + 2.0 * g + h);
        gxs += gx; gys += gy;
        mg += sqrt(gx * gx + gy * gy);
    }
    ogx = gxs; ogy = gys; omag = mg;
}

__device__ __noinline__ int orient_k_exact_g(const float* __restrict__ blurred,
                                             int Y, int X) {
    double gx, gy, m;
    sobel_exact_g(blurred, Y, X, gx, gy, m);
    const double orient = atan2(gy, gx) * RAD2DEG_D + 180.0;
    return (int)rint(orient / 45.0);
}

__device__ __noinline__ double mag_exact_g(const float* __restrict__ blurred,
                                           int Y, int X) {
    if (X < 0 || X >= IMG_W || Y < 0 || Y >= IMG_H) return 0.0;
    double gx, gy, m;
    sobel_exact_g(blurred, Y, X, gx, gy, m);
    return m;
}

// Packed direction tables (value+1 in nibbles, dir d at nibble 4d)
#define DX_PACK 0x21000122u
#define DY_PACK 0x00012221u
__device__ __forceinline__ int unpack_d(unsigned pack, int d) {
    return (int)((pack >> (4 * d)) & 0xFu) - 1;
}

// ===========================================================================
// Kernel A: fused separable blur, one barrier. (Unchanged from R15 — passed.)
//   hbuf[c][r][s]: h-sum at image (by0-2+r, bx0-2+s), r,s in 0..35.
// ===========================================================================
__device__ __forceinline__ void a1_task(float (*hbuf)[36][36],
                                        const float* __restrict__ img,
                                        float g0, float g1, float g2, float g3,
                                        float g4, int bx0, int by0, int t) {
    const int c = t / 324, rem = t - c * 324;
    const int r = rem / 9, g = rem - r * 9;
    const float* row = img + c * HW + (by0 - 2 + r) * IMG_W + (bx0 + 4 * g - 4);
    const float4 A = __ldg((const float4*)row);
    const float4 B = __ldg((const float4*)(row + 4));
    const float w[8] = {A.x, A.y, A.z, A.w, B.x, B.y, B.z, B.w};
    float o[4];
#pragma unroll
    for (int i = 0; i < 4; i++) {
        float v = g2 * w[i + 2];
        v = fmaf(g0, w[i],     v);
        v = fmaf(g1, w[i + 1], v);
        v = fmaf(g3, w[i + 3], v);
        v = fmaf(g4, w[i + 4], v);
        o[i] = v;
    }
    *(float4*)&hbuf[c][r][4 * g] = make_float4(o[0], o[1], o[2], o[3]);
}

__device__ __forceinline__ void a2_task(const float (*hbuf)[36][36],
                                        float* __restrict__ blurred,
                                        float g0, float g1, float g2, float g3,
                                        float g4, int bx0, int by0, int t) {
    const int c = t >> 8;
    const int rem = t & 255;
    const int y = rem >> 3, k = rem & 7;
    float e[5][4];
#pragma unroll
    for (int j = 0; j < 5; j++) {
        const float4 q0 = *(const float4*)&hbuf[c][y + j][4 * k];
        const float4 q1 = *(const float4*)&hbuf[c][y + j][4 * k + 4];
        e[j][0] = q0.z; e[j][1] = q0.w; e[j][2] = q1.x; e[j][3] = q1.y;
    }
    float4 o;
    o.x = fmaf(g4, e[4][0], fmaf(g3, e[3][0], fmaf(g2, e[2][0], fmaf(g1, e[1][0], g0 * e[0][0]))));
    o.y = fmaf(g4, e[4][1], fmaf(g3, e[3][1], fmaf(g2, e[2][1], fmaf(g1, e[1][1], g0 * e[0][1]))));
    o.z = fmaf(g4, e[4][2], fmaf(g3, e[3][2], fmaf(g2, e[2][2], fmaf(g1, e[1][2], g0 * e[0][2]))));
    o.w = fmaf(g4, e[4][3], fmaf(g3, e[3][3], fmaf(g2, e[2][3], fmaf(g1, e[1][3], g0 * e[0][3]))));
    *(float4*)&blurred[c * HW + (by0 + y) * IMG_W + bx0 + 4 * k] = o;
}

__global__ void __launch_bounds__(256, 6)
k_blur(const float* __restrict__ img, const float* __restrict__ g5,
       float* __restrict__ blurred) {
    __shared__ float hbuf[3][36][36];
    const int tid = threadIdx.x;
    const int bx0 = blockIdx.x * 32;
    const int by0 = blockIdx.y * 32;

    const float g0 = __ldg(g5 + 0), g1 = __ldg(g5 + 1), g2 = __ldg(g5 + 2),
                g3 = __ldg(g5 + 3), g4 = __ldg(g5 + 4);

    const bool interior = (bx0 != 0) && (bx0 != IMG_W - 32) &&
                          (by0 != 0) && (by0 != IMG_H - 32);
    if (interior) {
        a1_task(hbuf, img, g0, g1, g2, g3, g4, bx0, by0, tid);
        a1_task(hbuf, img, g0, g1, g2, g3, g4, bx0, by0, tid + 256);
        a1_task(hbuf, img, g0, g1, g2, g3, g4, bx0, by0, tid + 512);
        if (tid < 204)
            a1_task(hbuf, img, g0, g1, g2, g3, g4, bx0, by0, tid + 768);
    } else {
        for (int t = tid; t < 3888; t += 256) {
            const int c = t / 1296, rem = t - c * 1296;
            const int r = rem / 36, s = rem - r * 36;
            const int Y = by0 - 2 + r, X = bx0 - 2 + s;
            const float* src = img + c * HW;
            float v = g2 * ldz_g(src, Y, X);
            v = fmaf(g0, ldz_g(src, Y, X - 2), v);
            v = fmaf(g1, ldz_g(src, Y, X - 1), v);
            v = fmaf(g3, ldz_g(src, Y, X + 1), v);
            v = fmaf(g4, ldz_g(src, Y, X + 2), v);
            hbuf[c][r][s] = v;
        }
    }
    __syncthreads();

    a2_task(hbuf, blurred, g0, g1, g2, g3, g4, bx0, by0, tid);
    a2_task(hbuf, blurred, g0, g1, g2, g3, g4, bx0, by0, tid + 256);
    a2_task(hbuf, blurred, g0, g1, g2, g3, g4, bx0, by0, tid + 512);
}

// ===========================================================================
// Kernel B: stage blurred tile into smem (coalesced), then sobel + orientation
// + NMS from smem. Two barriers.
//   sblur[c][r][col]: blurred at (by0-2+r, bx0-4+col), r 0..35, col 0..43.
//   smag[r][sc]:      mag at (by0-1+r, bx0-5+sc),     r 0..33, sc 4..39.
//                     (central pixel (y,x): r=y+1, sc=x+5)
// ===========================================================================
__global__ void __launch_bounds__(256, 6)
k_sobnms(const float* __restrict__ blurred,
         float* __restrict__ mag_out, float* __restrict__ orient_out,
         float* __restrict__ early_out, float* __restrict__ thin_out,
         float* __restrict__ thresh_out) {
    __shared__ float sblur[3][36][44];
    __shared__ float smag[34][44];
    __shared__ signed char sk[32][32];

    const int tid = threadIdx.x;
    const int bx0 = blockIdx.x * 32;
    const int by0 = blockIdx.y * 32;

    const bool interior = (bx0 != 0) && (bx0 != IMG_W - 32) &&
                          (by0 != 0) && (by0 != IMG_H - 32);

    // ---- Stage S: stage the blurred tile (coalesced float4) ----
    if (interior) {
        // 3 x 36 x 11 = 1188 tasks
#pragma unroll
        for (int u = 0; u < 4; u++) {
            const int t = tid + 256 * u;
            const int c = t / 396, rem = t - c * 396;
            const int r = rem / 11, q = rem - r * 11;
            const float4 v = __ldg((const float4*)(blurred + c * HW +
                                   (by0 - 2 + r) * IMG_W + (bx0 - 4 + 4 * q)));
            *(float4*)&sblur[c][r][4 * q] = v;
        }
        if (tid < 1188 - 1024) {
            const int t = tid + 1024;
            const int c = t / 396, rem = t - c * 396;
            const int r = rem / 11, q = rem - r * 11;
            const float4 v = __ldg((const float4*)(blurred + c * HW +
                                   (by0 - 2 + r) * IMG_W + (bx0 - 4 + 4 * q)));
            *(float4*)&sblur[c][r][4 * q] = v;
        }
    } else {
        // scalar, zero-padded: 3 x 36 x 44 = 4752 tasks
        for (int t = tid; t < 4752; t += 256) {
            const int c = t / 1584, rem = t - c * 1584;
            const int r = rem / 44, col = rem - r * 44;
            sblur[c][r][col] = ldz_g(blurred + c * HW, by0 - 2 + r, bx0 - 4 + col);
        }
    }
    __syncthreads();

    // ---- Stage B: mag (34 x 9 groups of 4) + orientation for central px ----
    {
#pragma unroll
        for (int u = 0; u < 2; u++) {
            const int t = (u == 0) ? tid : tid + 256;
            if (u == 1 && tid >= 306 - 256) break;
            const int r = t / 9, q = t - 9 * r;    // r 0..33, q 0..8
            const int Y = by0 - 1 + r;
            const int Xs = bx0 - 1 + 4 * q;        // X of pixel i=0

            float m[4]  = {0.f, 0.f, 0.f, 0.f};
            float sx[4] = {0.f, 0.f, 0.f, 0.f};
            float sy[4] = {0.f, 0.f, 0.f, 0.f};
#pragma unroll
            for (int c = 0; c < 3; c++) {
                const float4 L0 = *(const float4*)&sblur[c][r][4 * q];
                const float4 R0 = *(const float4*)&sblur[c][r][4 * q + 4];
                const float4 L1 = *(const float4*)&sblur[c][r + 1][4 * q];
                const float4 R1 = *(const float4*)&sblur[c][r + 1][4 * q + 4];
                const float4 L2 = *(const float4*)&sblur[c][r + 2][4 * q];
                const float4 R2 = *(const float4*)&sblur[c][r + 2][4 * q + 4];
                const float w0[8] = {L0.x, L0.y, L0.z, L0.w, R0.x, R0.y, R0.z, R0.w};
                const float w1[8] = {L1.x, L1.y, L1.z, L1.w, R1.x, R1.y, R1.z, R1.w};
                const float w2[8] = {L2.x, L2.y, L2.z, L2.w, R2.x, R2.y, R2.z, R2.w};
#pragma unroll
                for (int i = 0; i < 4; i++) {
                    const float a  = w0[i + 2], b = w0[i + 3], cc = w0[i + 4];
                    const float d  = w1[i + 2], e = w1[i + 4];
                    const float f  = w2[i + 2], gg = w2[i + 3], h = w2[i + 4];
                    const float gx = (a - cc) + 2.0f * (d - e) + (f - h);
                    const float gy = (a + 2.0f * b + cc) - (f + 2.0f * gg + h);
                    m[i] += sqrt_approx(fmaf(gx, gx, gy * gy));
                    sx[i] += gx;
                    sy[i] += gy;
                }
            }
            // Border: zero mag outside image (matches zero-pad of the mag map)
            if (!interior) {
#pragma unroll
                for (int i = 0; i < 4; i++) {
                    const int X = Xs + i;
                    if (Y < 0 || Y >= IMG_H || X < 0 || X >= IMG_W) m[i] = 0.0f;
                }
            }
            *(float4*)&smag[r][4 * q + 4] = make_float4(m[0], m[1], m[2], m[3]);

            // orientation for central pixels: s = 4q+i in [1,32]
            if (r >= 1 && r < 33) {
                unsigned riskyMask = 0;
                int kq4[4];
#pragma unroll
                for (int i = 0; i < 4; i++) {
                    const float ax = fabsf(sx[i]), ay = fabsf(sy[i]);
                    const bool gxneg = sx[i] < 0.0f;
                    const bool gypos = (__float_as_int(sy[i]) >= 0);
                    int kq;
                    bool risky;
                    if (!gxneg) {
                        const float lo = T1_POS * ax, hi = T2_POS * ax;
                        risky = (fabsf(ay - lo) <= BAND1 * ax) ||
                                (fabsf(ay - hi) <= BAND2 * ax);
                        if (ay < lo)      kq = 4;
                        else if (ay < hi) kq = gypos ? 5 : 3;
                        else              kq = gypos ? 6 : 2;
                    } else {
                        const float lo = T1_NEG * ax, hi = T2_NEG * ax;
                        risky = (fabsf(ay - lo) <= BAND1 * ax) ||
                                (fabsf(ay - hi) <= BAND2 * ax) ||
                                (ay <= 1e-3f * ax);
                        if (ay < lo)      kq = gypos ? 8 : 0;
                        else if (ay < hi) kq = gypos ? 7 : 1;
                        else              kq = gypos ? 6 : 2;
                    }
                    if (risky) riskyMask |= (1u << i);
                    kq4[i] = kq;
                }
                if (riskyMask) {
#pragma unroll
                    for (int i = 0; i < 4; i++) {
                        if (riskyMask & (1u << i))
                            kq4[i] = orient_k_exact_g(blurred, Y, Xs + i);
                    }
                }
#pragma unroll
                for (int i = 0; i < 4; i++) {
                    const int s = 4 * q + i;
                    if (s >= 1 && s < 33)
                        sk[r - 1][s - 1] = (signed char)kq4[i];
                }
            }
        }
    }
    __syncthreads();

    // ---- Stage C: NMS + 5 vector output stores (256 tasks exactly) ----
    {
        const int y = tid >> 3, g = tid & 7;
        const int Y = by0 + y;
        const int Xb = bx0 + 4 * g;
        float vm[4], vo[4], ve[4], vt[4], vh[4];
#pragma unroll
        for (int i = 0; i < 4; i++) {
            const int x = 4 * g + i;
            const float m = smag[y + 1][x + 5];
            const int kq  = (int)sk[y][x];

            vm[i] = m;
            vo[i] = 45.0f * (float)kq;
            ve[i] = (m < THRESH) ? 0.0f : m;

            const int ip  = kq & 7;
            const int in_ = (kq + 4) & 7;
            const int pdy = unpack_d(DY_PACK, ip),  pdx = unpack_d(DX_PACK, ip);
            const int ndy = unpack_d(DY_PACK, in_), ndx = unpack_d(DX_PACK, in_);

            const float npos = smag[y + 1 + pdy][x + 5 + pdx];
            const float nneg = smag[y + 1 + ndy][x + 5 + ndx];
            const float sel_min = fminf(m - npos, m - nneg);

            bool is_max;
            const float eps = 4e-6f * fmaxf(m, 1.0f);
            if (fabsf(sel_min) > eps) {
                is_max = sel_min > 0.0f;
            } else {
                const double md = mag_exact_g(blurred, Y, Xb + i);
                const double dp = md - mag_exact_g(blurred, Y + pdy, Xb + i + pdx);
                const double dn = md - mag_exact_g(blurred, Y + ndy, Xb + i + ndx);
                is_max = fmin(dp, dn) > 0.0;
            }

            const float thin = is_max ? m : 0.0f;
            vt[i] = thin;
            vh[i] = (thin < THRESH) ? 0.0f : thin;
        }
        const int idx = Y * IMG_W + Xb;
        *(float4*)&mag_out[idx]    = make_float4(vm[0], vm[1], vm[2], vm[3]);
        *(float4*)&orient_out[idx] = make_float4(vo[0], vo[1], vo[2], vo[3]);
        *(float4*)&early_out[idx]  = make_float4(ve[0], ve[1], ve[2], ve[3]);
        *(float4*)&thin_out[idx]   = make_float4(vt[0], vt[1], vt[2], vt[3]);
        *(float4*)&thresh_out[idx] = make_float4(vh[0], vh[1], vh[2], vh[3]);
    }
}

// ---------------------------------------------------------------------------
// Output layout (concatenated reference tuple, fp32):
//   [0,3HW) blurred | [3HW,4HW) mag | [4HW,5HW) orient | [5HW,6HW) thin
//   [6HW,7HW) thresholded | [7HW,8HW) early
// ---------------------------------------------------------------------------
extern "C" void kernel_launch(void* const* d_in, const int* in_sizes, int n_in,
                              void* d_out, int out_size) {
    const float* img  = (const float*)d_in[0];
    const float* gh_w = (const float*)d_in[1];

    float* out      = (float*)d_out;
    float* blurred  = out;
    float* mag      = out + 3 * (size_t)HW;
    float* orient   = out + 4 * (size_t)HW;
    float* thin     = out + 5 * (size_t)HW;
    float* threshed = out + 6 * (size_t)HW;
    float* early    = out + 7 * (size_t)HW;

    dim3 block(256, 1, 1);
    dim3 grid(IMG_W / 32, IMG_H / 32, 1);
    k_blur<<<grid, block>>>(img, gh_w, blurred);
    k_sobnms<<<grid, block>>>(blurred, mag, orient, early, thin, threshed);
}

// round 17
// speedup vs baseline: 1.1552x; 1.1552x over previous
#include <cuda_runtime.h>
#include <math.h>

#define IMG_H 2048
#define IMG_W 2048
#define HW (IMG_H * IMG_W)
#define THRESH 10.0f

// 180 / 3.14159 (reference constant, NOT pi)
#define RAD2DEG_D 57.29582790879777437539

// Octant boundary tangents (see R7 derivation)
#define T1_POS 0.41421317376f
#define T2_POS 2.41420677f
#define T1_NEG 0.41421628f
#define T2_NEG 2.41422489f
#define BAND1 1.0e-3f
#define BAND2 6.0e-3f

#define FULLM 0xffffffffu

__device__ __forceinline__ float ldz_g(const float* __restrict__ p, int Y, int X) {
    return (Y >= 0 && Y < IMG_H && X >= 0 && X < IMG_W) ? __ldg(p + Y * IMG_W + X) : 0.0f;
}

__device__ __forceinline__ float sqrt_approx(float x) {
    float r;
    asm("sqrt.approx.f32 %0, %1;" : "=f"(r) : "f"(x));
    return r;
}

// ---------------------------------------------------------------------------
// Exact (fp64) helpers reading the global blurred map (zero-padded).
// ---------------------------------------------------------------------------
__device__ __noinline__ void sobel_exact_g(const float* __restrict__ blurred,
                                           int Y, int X,
                                           double& ogx, double& ogy, double& omag) {
    double gxs = 0.0, gys = 0.0, mg = 0.0;
#pragma unroll
    for (int c = 0; c < 3; c++) {
        const float* __restrict__ p = blurred + c * HW;
        const double a  = ldz_g(p, Y - 1, X - 1);
        const double b  = ldz_g(p, Y - 1, X    );
        const double cc = ldz_g(p, Y - 1, X + 1);
        const double d  = ldz_g(p, Y,     X - 1);
        const double e  = ldz_g(p, Y,     X + 1);
        const double f  = ldz_g(p, Y + 1, X - 1);
        const double g  = ldz_g(p, Y + 1, X    );
        const double h  = ldz_g(p, Y + 1, X + 1);
        const double gx = (a - cc) + 2.0 * (d - e) + (f - h);
        const double gy = (a + 2.0 * b + cc) - (f + 2.0 * g + h);
        gxs += gx; gys += gy;
        mg += sqrt(gx * gx + gy * gy);
    }
    ogx = gxs; ogy = gys; omag = mg;
}

__device__ __noinline__ int orient_k_exact_g(const float* __restrict__ blurred,
                                             int Y, int X) {
    double gx, gy, m;
    sobel_exact_g(blurred, Y, X, gx, gy, m);
    const double orient = atan2(gy, gx) * RAD2DEG_D + 180.0;
    return (int)rint(orient / 45.0);
}

__device__ __noinline__ double mag_exact_g(const float* __restrict__ blurred,
                                           int Y, int X) {
    if (X < 0 || X >= IMG_W || Y < 0 || Y >= IMG_H) return 0.0;
    double gx, gy, m;
    sobel_exact_g(blurred, Y, X, gx, gy, m);
    return m;
}

// Packed direction tables (value+1 in nibbles, dir d at nibble 4d)
#define DX_PACK 0x21000122u
#define DY_PACK 0x00012221u
__device__ __forceinline__ int unpack_d(unsigned pack, int d) {
    return (int)((pack >> (4 * d)) & 0xFu) - 1;
}

// ===========================================================================
// Kernel A: fused separable blur, one barrier. (Unchanged — proven.)
// ===========================================================================
__device__ __forceinline__ void a1_task(float (*hbuf)[36][36],
                                        const float* __restrict__ img,
                                        float g0, float g1, float g2, float g3,
                                        float g4, int bx0, int by0, int t) {
    const int c = t / 324, rem = t - c * 324;
    const int r = rem / 9, g = rem - r * 9;
    const float* row = img + c * HW + (by0 - 2 + r) * IMG_W + (bx0 + 4 * g - 4);
    const float4 A = __ldg((const float4*)row);
    const float4 B = __ldg((const float4*)(row + 4));
    const float w[8] = {A.x, A.y, A.z, A.w, B.x, B.y, B.z, B.w};
    float o[4];
#pragma unroll
    for (int i = 0; i < 4; i++) {
        float v = g2 * w[i + 2];
        v = fmaf(g0, w[i],     v);
        v = fmaf(g1, w[i + 1], v);
        v = fmaf(g3, w[i + 3], v);
        v = fmaf(g4, w[i + 4], v);
        o[i] = v;
    }
    *(float4*)&hbuf[c][r][4 * g] = make_float4(o[0], o[1], o[2], o[3]);
}

__device__ __forceinline__ void a2_task(const float (*hbuf)[36][36],
                                        float* __restrict__ blurred,
                                        float g0, float g1, float g2, float g3,
                                        float g4, int bx0, int by0, int t) {
    const int c = t >> 8;
    const int rem = t & 255;
    const int y = rem >> 3, k = rem & 7;
    float e[5][4];
#pragma unroll
    for (int j = 0; j < 5; j++) {
        const float4 q0 = *(const float4*)&hbuf[c][y + j][4 * k];
        const float4 q1 = *(const float4*)&hbuf[c][y + j][4 * k + 4];
        e[j][0] = q0.z; e[j][1] = q0.w; e[j][2] = q1.x; e[j][3] = q1.y;
    }
    float4 o;
    o.x = fmaf(g4, e[4][0], fmaf(g3, e[3][0], fmaf(g2, e[2][0], fmaf(g1, e[1][0], g0 * e[0][0]))));
    o.y = fmaf(g4, e[4][1], fmaf(g3, e[3][1], fmaf(g2, e[2][1], fmaf(g1, e[1][1], g0 * e[0][1]))));
    o.z = fmaf(g4, e[4][2], fmaf(g3, e[3][2], fmaf(g2, e[2][2], fmaf(g1, e[1][2], g0 * e[0][2]))));
    o.w = fmaf(g4, e[4][3], fmaf(g3, e[3][3], fmaf(g2, e[2][3], fmaf(g1, e[1][3], g0 * e[0][3]))));
    *(float4*)&blurred[c * HW + (by0 + y) * IMG_W + bx0 + 4 * k] = o;
}

__global__ void __launch_bounds__(256, 6)
k_blur(const float* __restrict__ img, const float* __restrict__ g5,
       float* __restrict__ blurred) {
    __shared__ float hbuf[3][36][36];
    const int tid = threadIdx.x;
    const int bx0 = blockIdx.x * 32;
    const int by0 = blockIdx.y * 32;

    const float g0 = __ldg(g5 + 0), g1 = __ldg(g5 + 1), g2 = __ldg(g5 + 2),
                g3 = __ldg(g5 + 3), g4 = __ldg(g5 + 4);

    const bool interior = (bx0 != 0) && (bx0 != IMG_W - 32) &&
                          (by0 != 0) && (by0 != IMG_H - 32);
    if (interior) {
        a1_task(hbuf, img, g0, g1, g2, g3, g4, bx0, by0, tid);
        a1_task(hbuf, img, g0, g1, g2, g3, g4, bx0, by0, tid + 256);
        a1_task(hbuf, img, g0, g1, g2, g3, g4, bx0, by0, tid + 512);
        if (tid < 204)
            a1_task(hbuf, img, g0, g1, g2, g3, g4, bx0, by0, tid + 768);
    } else {
        for (int t = tid; t < 3888; t += 256) {
            const int c = t / 1296, rem = t - c * 1296;
            const int r = rem / 36, s = rem - r * 36;
            const int Y = by0 - 2 + r, X = bx0 - 2 + s;
            const float* src = img + c * HW;
            float v = g2 * ldz_g(src, Y, X);
            v = fmaf(g0, ldz_g(src, Y, X - 2), v);
            v = fmaf(g1, ldz_g(src, Y, X - 1), v);
            v = fmaf(g3, ldz_g(src, Y, X + 1), v);
            v = fmaf(g4, ldz_g(src, Y, X + 2), v);
            hbuf[c][r][s] = v;
        }
    }
    __syncthreads();

    a2_task(hbuf, blurred, g0, g1, g2, g3, g4, bx0, by0, tid);
    a2_task(hbuf, blurred, g0, g1, g2, g3, g4, bx0, by0, tid + 256);
    a2_task(hbuf, blurred, g0, g1, g2, g3, g4, bx0, by0, tid + 512);
}

// ===========================================================================
// Kernel B (rolling): warp-autonomous sobel + orientation + NMS.
// Each warp: 28 output columns x 32 rows. Lane x = X0 - 2 + lane.
// Rings (registers): u/v row-sums (3 rows x 3 ch), mag (3 rows), k (3 rows).
// No barriers, no smem.
//   STRIPS_X = ceil(2048/28) = 74, STRIPS_Y = 2048/32 = 64 -> 4736 warps.
// ===========================================================================
#define STRIPS_X 74
#define OUTW 28

__global__ void __launch_bounds__(256, 4)
k_roll(const float* __restrict__ blurred,
       float* __restrict__ mag_out, float* __restrict__ orient_out,
       float* __restrict__ early_out, float* __restrict__ thin_out,
       float* __restrict__ thresh_out) {
    const int warp = blockIdx.x * 8 + (threadIdx.x >> 5);
    const int lane = threadIdx.x & 31;
    const int sxw = warp % STRIPS_X;
    const int syw = warp / STRIPS_X;
    const int X0 = sxw * OUTW;
    const int Y0 = syw * 32;
    const int x  = X0 - 2 + lane;
    const bool xin = (x >= 0) && (x < IMG_W);
    const bool outlane = (lane >= 2) && (lane <= 29) && (x < IMG_W);

    float u0[3], u1[3], u2[3], v0[3], v1[3], v2[3];
#pragma unroll
    for (int c = 0; c < 3; c++) {
        u0[c] = u1[c] = u2[c] = 0.0f;
        v0[c] = v1[c] = v2[c] = 0.0f;
    }
    float magA = 0.0f, magB = 0.0f, magC = 0.0f;
    int kB = 0, kC = 0;

    for (int it = 0; it < 36; ++it) {
        const int yl = Y0 - 2 + it;

        // ---- step 1: load new blurred row, build row sums via shuffles ----
#pragma unroll
        for (int c = 0; c < 3; c++) {
            float w = 0.0f;
            if (xin && yl >= 0 && yl < IMG_H)
                w = __ldg(blurred + c * HW + yl * IMG_W + x);
            const float wl = __shfl_up_sync(FULLM, w, 1);
            const float wr = __shfl_down_sync(FULLM, w, 1);
            u0[c] = u1[c]; u1[c] = u2[c];
            v0[c] = v1[c]; v1[c] = v2[c];
            u2[c] = wl + 2.0f * w + wr;   // (a + 2b + cc) tree
            v2[c] = wl - wr;              // (a - cc)
        }
        if (it < 2) continue;

        // ---- step 2: mag + orientation at row ym = yl-1 ----
        const int ym = yl - 1;
        float mg = 0.0f, sgx = 0.0f, sgy = 0.0f;
#pragma unroll
        for (int c = 0; c < 3; c++) {
            const float gx = v0[c] + 2.0f * v1[c] + v2[c];
            const float gy = u0[c] - u2[c];
            mg += sqrt_approx(fmaf(gx, gx, gy * gy));
            sgx += gx;
            sgy += gy;
        }
        if (!xin || ym < 0 || ym >= IMG_H) mg = 0.0f;  // zero-pad of mag map

        int kq = 0;
        if (outlane && ym >= Y0 && ym < Y0 + 32) {     // k only where output needs it
            const float ax = fabsf(sgx), ay = fabsf(sgy);
            const bool gxneg = sgx < 0.0f;
            const bool gypos = (__float_as_int(sgy) >= 0);
            bool risky;
            if (!gxneg) {
                const float lo = T1_POS * ax, hi = T2_POS * ax;
                risky = (fabsf(ay - lo) <= BAND1 * ax) ||
                        (fabsf(ay - hi) <= BAND2 * ax);
                if (ay < lo)      kq = 4;
                else if (ay < hi) kq = gypos ? 5 : 3;
                else              kq = gypos ? 6 : 2;
            } else {
                const float lo = T1_NEG * ax, hi = T2_NEG * ax;
                risky = (fabsf(ay - lo) <= BAND1 * ax) ||
                        (fabsf(ay - hi) <= BAND2 * ax) ||
                        (ay <= 1e-3f * ax);
                if (ay < lo)      kq = gypos ? 8 : 0;
                else if (ay < hi) kq = gypos ? 7 : 1;
                else              kq = gypos ? 6 : 2;
            }
            if (risky) kq = orient_k_exact_g(blurred, ym, x);
        }

        magA = magB; magB = magC; magC = mg;
        kB = kC; kC = kq;

        if (it < 4) continue;

        // ---- step 3: NMS + outputs at row yn = yl-2 ----
        const int yn = yl - 2;
        const float mlA = __shfl_up_sync(FULLM, magA, 1);
        const float mrA = __shfl_down_sync(FULLM, magA, 1);
        const float mlB = __shfl_up_sync(FULLM, magB, 1);
        const float mrB = __shfl_down_sync(FULLM, magB, 1);
        const float mlC = __shfl_up_sync(FULLM, magC, 1);
        const float mrC = __shfl_down_sync(FULLM, magC, 1);

        if (outlane) {
            const float m = magB;
            const int kq2 = kB;
            const int ip  = kq2 & 7;
            const int in_ = (kq2 + 4) & 7;
            const int pdy = unpack_d(DY_PACK, ip),  pdx = unpack_d(DX_PACK, ip);
            const int ndy = unpack_d(DY_PACK, in_), ndx = unpack_d(DX_PACK, in_);

            const float pA = (pdx < 0) ? mlA : (pdx > 0) ? mrA : magA;
            const float pB = (pdx < 0) ? mlB : (pdx > 0) ? mrB : magB;
            const float pC = (pdx < 0) ? mlC : (pdx > 0) ? mrC : magC;
            const float npos = (pdy < 0) ? pA : (pdy > 0) ? pC : pB;

            const float nA = (ndx < 0) ? mlA : (ndx > 0) ? mrA : magA;
            const float nB = (ndx < 0) ? mlB : (ndx > 0) ? mrB : magB;
            const float nC = (ndx < 0) ? mlC : (ndx > 0) ? mrC : magC;
            const float nneg = (ndy < 0) ? nA : (ndy > 0) ? nC : nB;

            const float sel_min = fminf(m - npos, m - nneg);
            bool is_max;
            const float eps = 4e-6f * fmaxf(m, 1.0f);
            if (fabsf(sel_min) > eps) {
                is_max = sel_min > 0.0f;
            } else {
                const double md = mag_exact_g(blurred, yn, x);
                const double dp = md - mag_exact_g(blurred, yn + pdy, x + pdx);
                const double dn = md - mag_exact_g(blurred, yn + ndy, x + ndx);
                is_max = fmin(dp, dn) > 0.0;
            }
            const float thin = is_max ? m : 0.0f;

            const int idx = yn * IMG_W + x;
            mag_out[idx]    = m;
            orient_out[idx] = 45.0f * (float)kq2;
            early_out[idx]  = (m < THRESH) ? 0.0f : m;
            thin_out[idx]   = thin;
            thresh_out[idx] = (thin < THRESH) ? 0.0f : thin;
        }
    }
}

// ---------------------------------------------------------------------------
// Output layout (concatenated reference tuple, fp32):
//   [0,3HW) blurred | [3HW,4HW) mag | [4HW,5HW) orient | [5HW,6HW) thin
//   [6HW,7HW) thresholded | [7HW,8HW) early
// ---------------------------------------------------------------------------
extern "C" void kernel_launch(void* const* d_in, const int* in_sizes, int n_in,
                              void* d_out, int out_size) {
    const float* img  = (const float*)d_in[0];
    const float* gh_w = (const float*)d_in[1];

    float* out      = (float*)d_out;
    float* blurred  = out;
    float* mag      = out + 3 * (size_t)HW;
    float* orient   = out + 4 * (size_t)HW;
    float* thin     = out + 5 * (size_t)HW;
    float* threshed = out + 6 * (size_t)HW;
    float* early    = out + 7 * (size_t)HW;

    {
        dim3 block(256, 1, 1);
        dim3 grid(IMG_W / 32, IMG_H / 32, 1);
        k_blur<<<grid, block>>>(img, gh_w, blurred);
    }
    {
        // 74 x 64 = 4736 warps, 8 warps per block -> 592 blocks
        k_roll<<<592, 256>>>(blurred, mag, orient, early, thin, threshed);
    }
}